// round 8
// baseline (speedup 1.0000x reference)
#include <cuda_runtime.h>
#include <cuda_bf16.h>

#define NVERT 4096
#define ROW_CAP 64            // per-row neighbor cap (true max degree ~ 40)
#define WPB 8                 // warps per block
#define NBLOCKS (NVERT / WPB) // 512: one warp per row, single wave

// -------- device scratch -----------------------------------------------------
// All state is self-resetting across graph replays:
//   g_sum* are zeroed by the last block's atomicExch read-out each launch;
//   g_done wraps to 0 via atom.inc's modulus.
__device__ float        g_sum0;
__device__ float        g_sum1;
__device__ unsigned int g_cnt_sum;
__device__ unsigned int g_done;

// ---------------------------------------------------------------------------
// Single kernel: warp-per-row fused scan + loss + atomic finalize.
// Warp w owns Laplacian row r: streams 32 coalesced float4/lane (4 batches
// of 8, MLP=8, .cs). Nonzeros (~12/row) feed 12 matvec accumulators and a
// per-warp shared neighbor list. Warp butterfly gives all lanes sub[r];
// lanes compute loss terms for mask entries (c, r) — exact coverage since L
// is symmetric. Block folds its 8 warp partials, atomicAdd's them into
// global sums (L2 atomics: no fence, no L1 flush), and the last block
// (atom.acq_rel.inc, self-wrapping) reads the totals with atomicExch
// (which also re-zeroes them for the next replay) and writes the output.
// ---------------------------------------------------------------------------
__global__ __launch_bounds__(256) void fused_scan_kernel(
    const float* __restrict__ L,
    const float* __restrict__ dx,
    const float* __restrict__ x,
    float* __restrict__ out)
{
    __shared__ unsigned int s_cnt [WPB];
    __shared__ unsigned int s_list[WPB][ROW_CAP];
    __shared__ float        s_par [WPB][3];

    const int wid  = threadIdx.x >> 5;
    const int lane = threadIdx.x & 31;
    if (lane == 0) s_cnt[wid] = 0u;
    __syncwarp();

    const int r = blockIdx.x * WPB + wid;
    const uint4* __restrict__ Lrow =
        reinterpret_cast<const uint4*>(L + (size_t)r * NVERT);

    const float* __restrict__ dx1 = dx + NVERT * 3;
    const float* __restrict__ x1  = x  + NVERT * 3;

    float s[12];
#pragma unroll
    for (int k = 0; k < 12; ++k) s[k] = 0.f;

    // 1024 float4 per row / 32 lanes = 32 per lane; 4 batches of 8 (MLP=8)
#pragma unroll
    for (int kb = 0; kb < 4; ++kb) {
        uint4 v[8];
#pragma unroll
        for (int m = 0; m < 8; ++m)
            v[m] = __ldcs(&Lrow[lane + (kb * 8 + m) * 32]);

#pragma unroll
        for (int m = 0; m < 8; ++m) {
            if ((v[m].x | v[m].y | v[m].z | v[m].w) != 0u) {  // rare (~0.3%)
                unsigned b[4] = {v[m].x, v[m].y, v[m].z, v[m].w};
                int j0 = (lane + (kb * 8 + m) * 32) * 4;
#pragma unroll
                for (int c = 0; c < 4; ++c) {
                    if (b[c] != 0u) {
                        int   j = j0 + c;
                        float w = __uint_as_float(b[c]);  // == 1.0f; mul for exactness
                        const float* p0 = dx  + j * 3;
                        const float* p1 = dx1 + j * 3;
                        const float* q0 = x   + j * 3;
                        const float* q1 = x1  + j * 3;
                        s[0] += w * p0[0]; s[1]  += w * p0[1]; s[2]  += w * p0[2];
                        s[3] += w * p1[0]; s[4]  += w * p1[1]; s[5]  += w * p1[2];
                        s[6] += w * q0[0]; s[7]  += w * q0[1]; s[8]  += w * q0[2];
                        s[9] += w * q1[0]; s[10] += w * q1[1]; s[11] += w * q1[2];
                        unsigned pos = atomicAdd(&s_cnt[wid], 1u);
                        if (pos < ROW_CAP) s_list[wid][pos] = (unsigned)j;
                    }
                }
            }
        }
    }

    // ---- warp butterfly reduce: every lane ends with the full 12 sums ----
#pragma unroll
    for (int k = 0; k < 12; ++k)
#pragma unroll
        for (int off = 16; off > 0; off >>= 1)
            s[k] += __shfl_xor_sync(0xffffffffu, s[k], off);
    __syncwarp();

    const unsigned cnt = min(s_cnt[wid], (unsigned)ROW_CAP);

    // ---- loss terms for this row's neighbors (degree may exceed 32) ----
    float a0 = 0.f, a1 = 0.f;
    for (unsigned k = lane; k < cnt; k += 32) {
        int c = (int)s_list[wid][k];
        // batch 0
        {
            float t0 = s[0] - dx[c * 3 + 0];
            float t1 = s[1] - dx[c * 3 + 1];
            float t2 = s[2] - dx[c * 3 + 2];
            float u0 = s[6] - x [c * 3 + 0];
            float u1 = s[7] - x [c * 3 + 1];
            float u2 = s[8] - x [c * 3 + 2];
            a0 += fabsf((u0*u0 + u1*u1 + u2*u2) - (t0*t0 + t1*t1 + t2*t2));
        }
        // batch 1
        {
            float t0 = s[3]  - dx1[c * 3 + 0];
            float t1 = s[4]  - dx1[c * 3 + 1];
            float t2 = s[5]  - dx1[c * 3 + 2];
            float u0 = s[9]  - x1 [c * 3 + 0];
            float u1 = s[10] - x1 [c * 3 + 1];
            float u2 = s[11] - x1 [c * 3 + 2];
            a1 += fabsf((u0*u0 + u1*u1 + u2*u2) - (t0*t0 + t1*t1 + t2*t2));
        }
    }
#pragma unroll
    for (int off = 16; off > 0; off >>= 1) {
        a0 += __shfl_down_sync(0xffffffffu, a0, off);
        a1 += __shfl_down_sync(0xffffffffu, a1, off);
    }
    if (lane == 0) {
        s_par[wid][0] = a0;
        s_par[wid][1] = a1;
        s_par[wid][2] = (float)cnt;
    }
    __syncthreads();

    // ---- fold 8 warp partials, publish via L2 atomics, last-block finish ----
    if (threadIdx.x == 0) {
        float t0 = 0.f, t1 = 0.f, tc = 0.f;
#pragma unroll
        for (int w = 0; w < WPB; ++w) {
            t0 += s_par[w][0]; t1 += s_par[w][1]; tc += s_par[w][2];
        }
        atomicAdd(&g_sum0, t0);
        atomicAdd(&g_sum1, t1);
        atomicAdd(&g_cnt_sum, (unsigned)tc);

        // acq_rel atomic inc: release orders our adds before it, acquire
        // orders the winner's reads after everyone else's adds. No fence,
        // no L1D flush. Wraps to 0 at NBLOCKS (replay-idempotent).
        unsigned old;
        asm volatile(
            "atom.acq_rel.gpu.global.inc.u32 %0, [%1], %2;"
            : "=r"(old)
            : "l"(&g_done), "r"((unsigned)(NBLOCKS - 1))
            : "memory");

        if (old == (unsigned)(NBLOCKS - 1)) {
            // Read-and-reset: atomicExch is an L2 RMW (no stale L1) and
            // leaves the accumulators zeroed for the next graph replay.
            float    f0 = atomicExch(&g_sum0, 0.f);
            float    f1 = atomicExch(&g_sum1, 0.f);
            unsigned nc = atomicExch(&g_cnt_sum, 0u);
            float    n  = (float)nc;
            out[0] = f0 / n;
            out[1] = f1 / n;
        }
    }
}

// -------- launch -------------------------------------------------------------
extern "C" void kernel_launch(void* const* d_in, const int* in_sizes, int n_in,
                              void* d_out, int out_size) {
    const float* lap = nullptr;
    const float* vecs[2] = {nullptr, nullptr};
    int vn = 0;
    for (int k = 0; k < n_in; ++k) {
        if (in_sizes[k] == NVERT * NVERT)
            lap = (const float*)d_in[k];
        else if (vn < 2)
            vecs[vn++] = (const float*)d_in[k];
    }
    if (!lap && n_in >= 3) lap = (const float*)d_in[2];
    const float* dx = vecs[0] ? vecs[0] : (const float*)d_in[0];
    const float* x  = vecs[1] ? vecs[1] : (const float*)d_in[1];
    float* out = (float*)d_out;

    fused_scan_kernel<<<NBLOCKS, 256>>>(lap, dx, x, out);
}